// round 2
// baseline (speedup 1.0000x reference)
#include <cuda_runtime.h>
#include <cuda_bf16.h>
#include <cstdint>

#define DM 1024
#define DS 16
#define NB 4
#define LS 2048
#define MR (NB*LS)      // 8192 rows
#define LC 128          // scan chunk length
#define NCH (LS/LC)     // 16 chunks

// ---------------- scratch (device globals; no allocations) ----------------
__device__ __nv_bfloat16 g_xn[MR*DM];          // layernormed x (bf16)
__device__ __nv_bfloat16 g_w1[2*DM*DM];        // in_w bf16
__device__ __nv_bfloat16 g_w2[DM*DM];          // out_w bf16
__device__ __nv_bfloat16 g_xproj[MR*DM];       // ssm input u
__device__ __nv_bfloat16 g_zs[MR*DM];          // silu(z)
__device__ __nv_bfloat16 g_gated[MR*DM];       // y * silu(z)
__device__ float g_Abar[DM*DS];
__device__ float g_cbdt[DM*DS];
__device__ float g_Apow[DM*DS];                // Abar^LC
__device__ float g_F[NCH*NB*DM*DS];            // chunk-local end states
__device__ float g_Sin[NCH*NB*DM*DS];          // chunk incoming states

// ---------------- prep: weight bf16 cast + SSM params ----------------
__global__ void prep_kernel(const float* __restrict__ in_w, const float* __restrict__ out_w,
                            const float* __restrict__ A_log, const float* __restrict__ Bp,
                            const float* __restrict__ Cp, const float* __restrict__ log_dt){
    int stride = gridDim.x*blockDim.x;
    const int n1 = 2*DM*DM, n2 = DM*DM, n3 = DM*DS;
    for(int i = blockIdx.x*blockDim.x + threadIdx.x; i < n1+n2+n3; i += stride){
        if(i < n1){
            g_w1[i] = __float2bfloat16_rn(in_w[i]);
        } else if(i < n1+n2){
            g_w2[i-n1] = __float2bfloat16_rn(out_w[i-n1]);
        } else {
            int j = i - n1 - n2;
            int d = j >> 4;
            float dt = fminf(fmaxf(expf(log_dt[d]), 1e-4f), 1.0f);
            float Ab = expf(-expf(A_log[j]) * dt);
            Ab = fminf(fmaxf(Ab, 1e-8f), 1.0f - 1e-8f);
            g_Abar[j] = Ab;
            g_cbdt[j] = Cp[j] * Bp[j] * dt;
            float p = Ab;
            #pragma unroll
            for(int q = 0; q < 7; q++) p = p*p;   // Abar^128
            g_Apow[j] = p;
        }
    }
}

// ---------------- layernorm (row = one block) ----------------
__global__ void ln_kernel(const float* __restrict__ x, const float* __restrict__ g,
                          const float* __restrict__ b){
    int r = blockIdx.x, t = threadIdx.x;
    float4 v = reinterpret_cast<const float4*>(x + (size_t)r*DM)[t];
    float s = v.x+v.y+v.z+v.w;
    float q = v.x*v.x + v.y*v.y + v.z*v.z + v.w*v.w;
    #pragma unroll
    for(int o = 16; o; o >>= 1){
        s += __shfl_xor_sync(0xffffffffu, s, o);
        q += __shfl_xor_sync(0xffffffffu, q, o);
    }
    __shared__ float ss[8], qs[8];
    int w = t >> 5, lane = t & 31;
    if(lane == 0){ ss[w] = s; qs[w] = q; }
    __syncthreads();
    s = 0.f; q = 0.f;
    #pragma unroll
    for(int i = 0; i < 8; i++){ s += ss[i]; q += qs[i]; }
    float mu  = s * (1.0f/DM);
    float var = q * (1.0f/DM) - mu*mu;
    float rs  = rsqrtf(var + 1e-5f);
    float4 gv = reinterpret_cast<const float4*>(g)[t];
    float4 bv = reinterpret_cast<const float4*>(b)[t];
    float o0 = (v.x-mu)*rs*gv.x + bv.x;
    float o1 = (v.y-mu)*rs*gv.y + bv.y;
    float o2 = (v.z-mu)*rs*gv.z + bv.z;
    float o3 = (v.w-mu)*rs*gv.w + bv.w;
    __nv_bfloat162 p0 = __floats2bfloat162_rn(o0, o1);
    __nv_bfloat162 p1 = __floats2bfloat162_rn(o2, o3);
    uint2 pk; pk.x = *(uint32_t*)&p0; pk.y = *(uint32_t*)&p1;
    reinterpret_cast<uint2*>(g_xn + (size_t)r*DM)[t] = pk;
}

// ---------------- GEMM: C = A[M,K] * B[N,K]^T (+ fused epilogues) ----------------
__device__ __forceinline__ void cp16(uint32_t s, const void* g){
    asm volatile("cp.async.cg.shared.global [%0], [%1], 16;\n" :: "r"(s), "l"(g));
}

// MODE 0: xz = xn @ in_w^T + in_b ; split into xproj / silu(z) (bf16 out)
// MODE 1: out = gated @ out_w^T + out_b + residual, clip, fp32 out
template<int MODE>
__global__ void __launch_bounds__(256) gemm_kernel(const float* __restrict__ bias,
                                                   const float* __restrict__ resid,
                                                   float* __restrict__ outp){
    constexpr int K = DM;
    const __nv_bfloat16* __restrict__ A  = (MODE==0) ? g_xn : g_gated;
    const __nv_bfloat16* __restrict__ Bm = (MODE==0) ? g_w1 : g_w2;

    __shared__ __align__(16) __nv_bfloat16 As[2][128*40];  // pitch 40 halves (80B, conflict-free)
    __shared__ __align__(16) __nv_bfloat16 Bs[2][128*40];

    int t = threadIdx.x;
    int m0 = blockIdx.y * 128, n0 = blockIdx.x * 128;
    int lane = t & 31, wid = t >> 5;
    int wm = wid >> 2, wn = wid & 3;             // 2 x 4 warp grid, warp tile 64x32
    int grp = lane >> 2, c2 = (lane & 3) * 2;

    uint32_t sA = (uint32_t)__cvta_generic_to_shared(&As[0][0]);
    uint32_t sB = (uint32_t)__cvta_generic_to_shared(&Bs[0][0]);
    int lrow = t >> 2, lch = t & 3;

    float acc[4][4][4];
    #pragma unroll
    for(int i=0;i<4;i++)
    #pragma unroll
    for(int j=0;j<4;j++)
    #pragma unroll
    for(int q=0;q<4;q++) acc[i][j][q] = 0.f;

    auto load_stage = [&](int st, int kt){
        int k0 = kt * 32;
        #pragma unroll
        for(int i = 0; i < 2; i++){
            int r = lrow + i*64;
            cp16(sA + (uint32_t)(st*128*40 + r*40 + lch*8)*2,
                 A  + (size_t)(m0 + r)*K + k0 + lch*8);
            cp16(sB + (uint32_t)(st*128*40 + r*40 + lch*8)*2,
                 Bm + (size_t)(n0 + r)*K + k0 + lch*8);
        }
    };

    load_stage(0, 0);
    asm volatile("cp.async.commit_group;\n");
    const int KT = K / 32;
    for(int kt = 0; kt < KT; ++kt){
        if(kt + 1 < KT){
            load_stage((kt+1)&1, kt+1);
            asm volatile("cp.async.commit_group;\n");
            asm volatile("cp.async.wait_group 1;\n");
        } else {
            asm volatile("cp.async.wait_group 0;\n");
        }
        __syncthreads();
        int st = kt & 1;
        #pragma unroll
        for(int ks = 0; ks < 32; ks += 16){
            uint32_t af[4][4], bfr[4][2];
            #pragma unroll
            for(int mi = 0; mi < 4; mi++){
                int r = wm*64 + mi*16 + grp;
                const __nv_bfloat16* base = &As[st][0];
                af[mi][0] = *(const uint32_t*)&base[ r   *40 + ks + c2    ];
                af[mi][1] = *(const uint32_t*)&base[(r+8)*40 + ks + c2    ];
                af[mi][2] = *(const uint32_t*)&base[ r   *40 + ks + c2 + 8];
                af[mi][3] = *(const uint32_t*)&base[(r+8)*40 + ks + c2 + 8];
            }
            #pragma unroll
            for(int ni = 0; ni < 4; ni++){
                int rn = wn*32 + ni*8 + grp;
                const __nv_bfloat16* base = &Bs[st][0];
                bfr[ni][0] = *(const uint32_t*)&base[rn*40 + ks + c2    ];
                bfr[ni][1] = *(const uint32_t*)&base[rn*40 + ks + c2 + 8];
            }
            #pragma unroll
            for(int mi = 0; mi < 4; mi++)
            #pragma unroll
            for(int ni = 0; ni < 4; ni++){
                asm volatile(
                    "mma.sync.aligned.m16n8k16.row.col.f32.bf16.bf16.f32 "
                    "{%0,%1,%2,%3}, {%4,%5,%6,%7}, {%8,%9}, {%0,%1,%2,%3};\n"
                    : "+f"(acc[mi][ni][0]), "+f"(acc[mi][ni][1]),
                      "+f"(acc[mi][ni][2]), "+f"(acc[mi][ni][3])
                    : "r"(af[mi][0]), "r"(af[mi][1]), "r"(af[mi][2]), "r"(af[mi][3]),
                      "r"(bfr[ni][0]), "r"(bfr[ni][1]));
            }
        }
        __syncthreads();
    }

    // epilogue
    #pragma unroll
    for(int mi = 0; mi < 4; mi++){
        #pragma unroll
        for(int ni = 0; ni < 4; ni++){
            int row = m0 + wm*64 + mi*16 + grp;
            int col = n0 + wn*32 + ni*8 + c2;
            float b0 = bias[col], b1 = bias[col+1];
            #pragma unroll
            for(int h = 0; h < 2; h++){
                int rr = row + h*8;
                float v0 = acc[mi][ni][2*h+0] + b0;
                float v1 = acc[mi][ni][2*h+1] + b1;
                if(MODE == 0){
                    if(n0 >= DM){ // z half -> silu
                        v0 = v0 / (1.f + expf(-v0));
                        v1 = v1 / (1.f + expf(-v1));
                        __nv_bfloat162 p = __floats2bfloat162_rn(v0, v1);
                        *(uint32_t*)&g_zs[(size_t)rr*DM + col - DM] = *(uint32_t*)&p;
                    } else {
                        __nv_bfloat162 p = __floats2bfloat162_rn(v0, v1);
                        *(uint32_t*)&g_xproj[(size_t)rr*DM + col] = *(uint32_t*)&p;
                    }
                } else {
                    float2 rv = *(const float2*)&resid[(size_t)rr*DM + col];
                    v0 = fminf(fmaxf(v0 + rv.x, -10.f), 10.f);
                    v1 = fminf(fmaxf(v1 + rv.y, -10.f), 10.f);
                    float2 ov; ov.x = v0; ov.y = v1;
                    *(float2*)&outp[(size_t)rr*DM + col] = ov;
                }
            }
        }
    }
}

// ---------------- SSM chunked scan ----------------
// pass1: per (b, d, chunk) compute chunk-local end state (zero init)
__global__ void ssm_pass1(){
    int d = blockIdx.x*blockDim.x + threadIdx.x;
    int c = blockIdx.y, b = blockIdx.z;
    float Aa[DS];
    const float4* A4 = reinterpret_cast<const float4*>(g_Abar + d*DS);
    #pragma unroll
    for(int j=0;j<4;j++){ float4 v=A4[j]; Aa[4*j]=v.x; Aa[4*j+1]=v.y; Aa[4*j+2]=v.z; Aa[4*j+3]=v.w; }
    float s[DS];
    #pragma unroll
    for(int n=0;n<DS;n++) s[n] = 0.f;
    const __nv_bfloat16* u = g_xproj + (size_t)(b*LS + c*LC)*DM + d;
    #pragma unroll 4
    for(int tt = 0; tt < LC; ++tt){
        float uv = __bfloat162float(u[(size_t)tt*DM]);
        #pragma unroll
        for(int n=0;n<DS;n++) s[n] = fmaf(Aa[n], s[n], uv);
    }
    float4* F4 = reinterpret_cast<float4*>(g_F + (size_t)((c*NB + b)*DM + d)*DS);
    #pragma unroll
    for(int j=0;j<4;j++){ float4 v; v.x=s[4*j]; v.y=s[4*j+1]; v.z=s[4*j+2]; v.w=s[4*j+3]; F4[j]=v; }
}

// pass2: sequential combine across the 16 chunks -> incoming state per chunk
__global__ void ssm_pass2(){
    int i = blockIdx.x*blockDim.x + threadIdx.x;      // over NB*DM*DS = 65536
    float Ap = g_Apow[i & (DM*DS - 1)];
    float s = 0.f;
    #pragma unroll
    for(int c = 0; c < NCH; c++){
        g_Sin[c*(NB*DM*DS) + i] = s;
        s = fmaf(Ap, s, g_F[c*(NB*DM*DS) + i]);
    }
}

// pass3: replay chunk with true incoming state, emit y * silu(z) (bf16)
__global__ void ssm_pass3(){
    int d = blockIdx.x*blockDim.x + threadIdx.x;
    int c = blockIdx.y, b = blockIdx.z;
    float Aa[DS], cb[DS], s[DS];
    const float4* A4 = reinterpret_cast<const float4*>(g_Abar + d*DS);
    const float4* C4 = reinterpret_cast<const float4*>(g_cbdt + d*DS);
    const float4* S4 = reinterpret_cast<const float4*>(g_Sin + (size_t)c*(NB*DM*DS) + (size_t)(b*DM + d)*DS);
    #pragma unroll
    for(int j=0;j<4;j++){
        float4 va=A4[j]; Aa[4*j]=va.x; Aa[4*j+1]=va.y; Aa[4*j+2]=va.z; Aa[4*j+3]=va.w;
        float4 vc=C4[j]; cb[4*j]=vc.x; cb[4*j+1]=vc.y; cb[4*j+2]=vc.z; cb[4*j+3]=vc.w;
        float4 vs=S4[j]; s[4*j]=vs.x;  s[4*j+1]=vs.y;  s[4*j+2]=vs.z;  s[4*j+3]=vs.w;
    }
    size_t base = (size_t)(b*LS + c*LC)*DM + d;
    const __nv_bfloat16* u  = g_xproj + base;
    const __nv_bfloat16* zp = g_zs    + base;
    __nv_bfloat16*       gp = g_gated + base;
    #pragma unroll 2
    for(int tt = 0; tt < LC; ++tt){
        float uv = __bfloat162float(u[(size_t)tt*DM]);
        #pragma unroll
        for(int n=0;n<DS;n++) s[n] = fmaf(Aa[n], s[n], uv);
        float y = 0.f;
        #pragma unroll
        for(int n=0;n<DS;n++) y = fmaf(cb[n], s[n], y);
        float zv = __bfloat162float(zp[(size_t)tt*DM]);
        gp[(size_t)tt*DM] = __float2bfloat16_rn(y * zv);
    }
}

// ---------------- launch ----------------
extern "C" void kernel_launch(void* const* d_in, const int* in_sizes, int n_in,
                              void* d_out, int out_size){
    const float* x      = (const float*)d_in[0];
    const float* A_log  = (const float*)d_in[1];
    const float* Bp     = (const float*)d_in[2];
    const float* Cp     = (const float*)d_in[3];
    const float* log_dt = (const float*)d_in[4];
    const float* in_w   = (const float*)d_in[5];
    const float* in_b   = (const float*)d_in[6];
    const float* out_w  = (const float*)d_in[7];
    const float* out_b  = (const float*)d_in[8];
    const float* ln_g   = (const float*)d_in[9];
    const float* ln_b   = (const float*)d_in[10];
    float* outp = (float*)d_out;

    prep_kernel<<<512, 256>>>(in_w, out_w, A_log, Bp, Cp, log_dt);
    ln_kernel<<<MR, 256>>>(x, ln_g, ln_b);
    gemm_kernel<0><<<dim3(2*DM/128, MR/128), 256>>>(in_b, nullptr, nullptr);
    ssm_pass1<<<dim3(DM/256, NCH, NB), 256>>>();
    ssm_pass2<<<(NB*DM*DS)/256, 256>>>();
    ssm_pass3<<<dim3(DM/256, NCH, NB), 256>>>();
    gemm_kernel<1><<<dim3(DM/128, MR/128), 256>>>(out_b, x, outp);
}

// round 4
// speedup vs baseline: 1.0020x; 1.0020x over previous
#include <cuda_runtime.h>
#include <cuda_bf16.h>
#include <cstdint>

#define DM 1024
#define DS 16
#define NB 4
#define LS 2048
#define MR (NB*LS)      // 8192 rows
#define LC 32           // scan chunk length
#define NCH (LS/LC)     // 64 chunks

// ---------------- scratch (device globals; no allocations) ----------------
__device__ __align__(256) __nv_bfloat16 g_xn[MR*DM];     // layernormed x (bf16)
__device__ __align__(256) __nv_bfloat16 g_w1[2*DM*DM];   // in_w bf16
__device__ __align__(256) __nv_bfloat16 g_w2[DM*DM];     // out_w bf16
__device__ __align__(256) __nv_bfloat16 g_xproj[MR*DM];  // ssm input u
__device__ __align__(256) __nv_bfloat16 g_zs[MR*DM];     // silu(z)
__device__ __align__(256) __nv_bfloat16 g_gated[MR*DM];  // y * silu(z)
__device__ __align__(256) float g_Abar[DM*DS];
__device__ __align__(256) float g_cbdt[DM*DS];
__device__ __align__(256) float g_Apow[DM*DS];           // Abar^LC
__device__ __align__(256) float g_F[NCH*NB*DM*DS];       // chunk-local end states
__device__ __align__(256) float g_Sin[NCH*NB*DM*DS];     // chunk incoming states

// ---------------- PTX helpers ----------------
__device__ __forceinline__ void cp16(uint32_t s, const void* g){
    asm volatile("cp.async.cg.shared.global [%0], [%1], 16;\n" :: "r"(s), "l"(g));
}
#define LDSM4(v, addr) \
    asm volatile("ldmatrix.sync.aligned.m8n8.x4.shared.b16 {%0,%1,%2,%3}, [%4];" \
        : "=r"((v)[0]), "=r"((v)[1]), "=r"((v)[2]), "=r"((v)[3]) : "r"(addr))
#define MMA16816(d, a, b0, b1) \
    asm volatile("mma.sync.aligned.m16n8k16.row.col.f32.bf16.bf16.f32 " \
        "{%0,%1,%2,%3},{%4,%5,%6,%7},{%8,%9},{%0,%1,%2,%3};" \
        : "+f"((d)[0]), "+f"((d)[1]), "+f"((d)[2]), "+f"((d)[3]) \
        : "r"((a)[0]), "r"((a)[1]), "r"((a)[2]), "r"((a)[3]), "r"(b0), "r"(b1))

// ---------------- prep: weight bf16 cast + SSM params ----------------
__global__ void prep_kernel(const float* __restrict__ in_w, const float* __restrict__ out_w,
                            const float* __restrict__ A_log, const float* __restrict__ Bp,
                            const float* __restrict__ Cp, const float* __restrict__ log_dt){
    int stride = gridDim.x*blockDim.x;
    const int n1 = 2*DM*DM, n2 = DM*DM, n3 = DM*DS;
    for(int i = blockIdx.x*blockDim.x + threadIdx.x; i < n1+n2+n3; i += stride){
        if(i < n1){
            g_w1[i] = __float2bfloat16_rn(in_w[i]);
        } else if(i < n1+n2){
            g_w2[i-n1] = __float2bfloat16_rn(out_w[i-n1]);
        } else {
            int j = i - n1 - n2;
            int d = j >> 4;
            float dt = fminf(fmaxf(expf(log_dt[d]), 1e-4f), 1.0f);
            float Ab = expf(-expf(A_log[j]) * dt);
            Ab = fminf(fmaxf(Ab, 1e-8f), 1.0f - 1e-8f);
            g_Abar[j] = Ab;
            g_cbdt[j] = Cp[j] * Bp[j] * dt;
            float p = Ab;
            #pragma unroll
            for(int q = 0; q < 5; q++) p = p*p;   // Abar^32 (LC=32)
            g_Apow[j] = p;
        }
    }
}

// ---------------- layernorm (row = one block) ----------------
__global__ void ln_kernel(const float* __restrict__ x, const float* __restrict__ g,
                          const float* __restrict__ b){
    int r = blockIdx.x, t = threadIdx.x;
    float4 v = reinterpret_cast<const float4*>(x + (size_t)r*DM)[t];
    float s = v.x+v.y+v.z+v.w;
    float q = v.x*v.x + v.y*v.y + v.z*v.z + v.w*v.w;
    #pragma unroll
    for(int o = 16; o; o >>= 1){
        s += __shfl_xor_sync(0xffffffffu, s, o);
        q += __shfl_xor_sync(0xffffffffu, q, o);
    }
    __shared__ float ss[8], qs[8];
    int w = t >> 5, lane = t & 31;
    if(lane == 0){ ss[w] = s; qs[w] = q; }
    __syncthreads();
    s = 0.f; q = 0.f;
    #pragma unroll
    for(int i = 0; i < 8; i++){ s += ss[i]; q += qs[i]; }
    float mu  = s * (1.0f/DM);
    float var = q * (1.0f/DM) - mu*mu;
    float rs  = rsqrtf(var + 1e-5f);
    float4 gv = reinterpret_cast<const float4*>(g)[t];
    float4 bv = reinterpret_cast<const float4*>(b)[t];
    float o0 = (v.x-mu)*rs*gv.x + bv.x;
    float o1 = (v.y-mu)*rs*gv.y + bv.y;
    float o2 = (v.z-mu)*rs*gv.z + bv.z;
    float o3 = (v.w-mu)*rs*gv.w + bv.w;
    __nv_bfloat162 p0 = __floats2bfloat162_rn(o0, o1);
    __nv_bfloat162 p1 = __floats2bfloat162_rn(o2, o3);
    uint2 pk; pk.x = *(uint32_t*)&p0; pk.y = *(uint32_t*)&p1;
    reinterpret_cast<uint2*>(g_xn + (size_t)r*DM)[t] = pk;
}

// ---------------- HMMA GEMM: C[M,N] = A[M,K] @ B[N,K]^T + fused epilogue ------
// CTA tile 128(M) x 256(N), 8 warps (warp tile 64x64), K chunks of 32,
// 3-stage cp.async pipeline, ldmatrix.x4 fragments, XOR-swizzled smem.
// MODE 0: xz = xn @ in_w^T + in_b ; split + silu, bf16 out
// MODE 1: out = gated @ out_w^T + out_b + resid, clip, fp32 out
#define STG_BYTES 24576          // 8KB A + 16KB B
#define GEMM_SMEM (3*STG_BYTES + 128)

template<int MODE>
__global__ void __launch_bounds__(256) gemm_hmma(const float* __restrict__ bias,
                                                 const float* __restrict__ resid,
                                                 float* __restrict__ outp){
    constexpr int K = DM, KB = K*2;
    const __nv_bfloat16* __restrict__ Am = (MODE==0) ? g_xn : g_gated;
    const __nv_bfloat16* __restrict__ Bm = (MODE==0) ? g_w1 : g_w2;

    extern __shared__ char smem_dyn[];
    uint32_t sbase = (uint32_t)__cvta_generic_to_shared(smem_dyn);
    sbase = (sbase + 127) & ~127u;

    int t = threadIdx.x, lane = t & 31, wid = t >> 5;
    int wm = wid >> 2, wn = wid & 3;             // 2 x 4 warps over 128x256
    int m0 = blockIdx.y * 128, n0 = blockIdx.x * 256;

    const char* gA = (const char*)Am + (size_t)m0 * KB;
    const char* gB = (const char*)Bm + (size_t)n0 * KB;

    auto load = [&](int k, int st){
        uint32_t sA = sbase + (uint32_t)st*STG_BYTES;
        uint32_t sB = sA + 8192;
        int koff = k*64;                          // bytes (32 bf16)
        #pragma unroll
        for(int i = 0; i < 2; i++){               // A: 128 rows x 4 chunks
            int ci = t + i*256;
            int r = ci >> 2, c = ci & 3;
            cp16(sA + (uint32_t)(r*64 + ((c ^ ((r>>1)&3))<<4)),
                 gA + (size_t)r*KB + koff + c*16);
        }
        #pragma unroll
        for(int i = 0; i < 4; i++){               // B: 256 rows x 4 chunks
            int ci = t + i*256;
            int r = ci >> 2, c = ci & 3;
            cp16(sB + (uint32_t)(r*64 + ((c ^ ((r>>1)&3))<<4)),
                 gB + (size_t)r*KB + koff + c*16);
        }
    };

    float acc[4][8][4];
    #pragma unroll
    for(int i=0;i<4;i++)
    #pragma unroll
    for(int j=0;j<8;j++)
    #pragma unroll
    for(int q=0;q<4;q++) acc[i][j][q] = 0.f;

    load(0, 0); asm volatile("cp.async.commit_group;");
    load(1, 1); asm volatile("cp.async.commit_group;");

    int la_r = lane & 15, la_k = lane >> 4;
    uint32_t sw = (uint32_t)((la_r >> 1) & 3);
    uint32_t aoff = (uint32_t)((wm*64 + la_r) * 64);
    uint32_t boff = (uint32_t)((wn*64 + la_r) * 64);

    #pragma unroll 1
    for(int k = 0; k < K/32; k++){
        int st = k % 3;
        asm volatile("cp.async.wait_group 1;");
        __syncthreads();
        uint32_t sA = sbase + (uint32_t)st*STG_BYTES + aoff;
        uint32_t sB = sbase + (uint32_t)st*STG_BYTES + 8192 + boff;
        #pragma unroll
        for(int ks = 0; ks < 2; ks++){
            uint32_t kx = (uint32_t)(((ks*2 + la_k) ^ sw) << 4);
            uint32_t a[4][4], b[4][4];
            #pragma unroll
            for(int mi = 0; mi < 4; mi++) LDSM4(a[mi], sA + mi*1024 + kx);
            #pragma unroll
            for(int ng = 0; ng < 4; ng++) LDSM4(b[ng], sB + ng*1024 + kx);
            #pragma unroll
            for(int mi = 0; mi < 4; mi++)
            #pragma unroll
            for(int ng = 0; ng < 4; ng++){
                MMA16816(acc[mi][2*ng],   a[mi], b[ng][0], b[ng][2]);
                MMA16816(acc[mi][2*ng+1], a[mi], b[ng][1], b[ng][3]);
            }
        }
        if(k + 2 < K/32) load(k + 2, (k + 2) % 3);
        asm volatile("cp.async.commit_group;");
    }

    // ---------------- epilogue (direct global stores) ----------------
    int grp = lane >> 2, c2 = (lane & 3) * 2;
    #pragma unroll
    for(int mi = 0; mi < 4; mi++){
        #pragma unroll
        for(int ni = 0; ni < 8; ni++){
            int row = m0 + wm*64 + mi*16 + grp;
            int col = n0 + wn*64 + ni*8 + c2;
            float b0 = __ldg(&bias[col]), b1 = __ldg(&bias[col+1]);
            #pragma unroll
            for(int h = 0; h < 2; h++){
                int rr = row + h*8;
                float v0 = acc[mi][ni][2*h+0] + b0;
                float v1 = acc[mi][ni][2*h+1] + b1;
                if(MODE == 0){
                    if(n0 >= DM){
                        v0 = v0 / (1.f + __expf(-v0));
                        v1 = v1 / (1.f + __expf(-v1));
                        __nv_bfloat162 p = __floats2bfloat162_rn(v0, v1);
                        *(uint32_t*)&g_zs[(size_t)rr*DM + col - DM] = *(uint32_t*)&p;
                    } else {
                        __nv_bfloat162 p = __floats2bfloat162_rn(v0, v1);
                        *(uint32_t*)&g_xproj[(size_t)rr*DM + col] = *(uint32_t*)&p;
                    }
                } else {
                    float2 rv = *(const float2*)&resid[(size_t)rr*DM + col];
                    v0 = fminf(fmaxf(v0 + rv.x, -10.f), 10.f);
                    v1 = fminf(fmaxf(v1 + rv.y, -10.f), 10.f);
                    float2 ov; ov.x = v0; ov.y = v1;
                    *(float2*)&outp[(size_t)rr*DM + col] = ov;
                }
            }
        }
    }
}

// ---------------- SSM chunked scan ----------------
__global__ void ssm_pass1(){
    int d = blockIdx.x*blockDim.x + threadIdx.x;
    int c = blockIdx.y, b = blockIdx.z;
    float Aa[DS];
    const float4* A4 = reinterpret_cast<const float4*>(g_Abar + d*DS);
    #pragma unroll
    for(int j=0;j<4;j++){ float4 v=A4[j]; Aa[4*j]=v.x; Aa[4*j+1]=v.y; Aa[4*j+2]=v.z; Aa[4*j+3]=v.w; }
    float s[DS];
    #pragma unroll
    for(int n=0;n<DS;n++) s[n] = 0.f;
    const __nv_bfloat16* u = g_xproj + (size_t)(b*LS + c*LC)*DM + d;
    #pragma unroll 4
    for(int tt = 0; tt < LC; ++tt){
        float uv = __bfloat162float(u[(size_t)tt*DM]);
        #pragma unroll
        for(int n=0;n<DS;n++) s[n] = fmaf(Aa[n], s[n], uv);
    }
    float4* F4 = reinterpret_cast<float4*>(g_F + (size_t)((c*NB + b)*DM + d)*DS);
    #pragma unroll
    for(int j=0;j<4;j++){ float4 v; v.x=s[4*j]; v.y=s[4*j+1]; v.z=s[4*j+2]; v.w=s[4*j+3]; F4[j]=v; }
}

__global__ void ssm_pass2(){
    int i = blockIdx.x*blockDim.x + threadIdx.x;      // over NB*DM*DS = 65536
    float Ap = g_Apow[i & (DM*DS - 1)];
    float s = 0.f;
    #pragma unroll 8
    for(int c = 0; c < NCH; c++){
        g_Sin[c*(NB*DM*DS) + i] = s;
        s = fmaf(Ap, s, g_F[c*(NB*DM*DS) + i]);
    }
}

__global__ void ssm_pass3(){
    int d = blockIdx.x*blockDim.x + threadIdx.x;
    int c = blockIdx.y, b = blockIdx.z;
    float Aa[DS], cb[DS], s[DS];
    const float4* A4 = reinterpret_cast<const float4*>(g_Abar + d*DS);
    const float4* C4 = reinterpret_cast<const float4*>(g_cbdt + d*DS);
    const float4* S4 = reinterpret_cast<const float4*>(g_Sin + (size_t)c*(NB*DM*DS) + (size_t)(b*DM + d)*DS);
    #pragma unroll
    for(int j=0;j<4;j++){
        float4 va=A4[j]; Aa[4*j]=va.x; Aa[4*j+1]=va.y; Aa[4*j+2]=va.z; Aa[4*j+3]=va.w;
        float4 vc=C4[j]; cb[4*j]=vc.x; cb[4*j+1]=vc.y; cb[4*j+2]=vc.z; cb[4*j+3]=vc.w;
        float4 vs=S4[j]; s[4*j]=vs.x;  s[4*j+1]=vs.y;  s[4*j+2]=vs.z;  s[4*j+3]=vs.w;
    }
    size_t base = (size_t)(b*LS + c*LC)*DM + d;
    const __nv_bfloat16* u  = g_xproj + base;
    const __nv_bfloat16* zp = g_zs    + base;
    __nv_bfloat16*       gp = g_gated + base;
    #pragma unroll 2
    for(int tt = 0; tt < LC; ++tt){
        float uv = __bfloat162float(u[(size_t)tt*DM]);
        #pragma unroll
        for(int n=0;n<DS;n++) s[n] = fmaf(Aa[n], s[n], uv);
        float y = 0.f;
        #pragma unroll
        for(int n=0;n<DS;n++) y = fmaf(cb[n], s[n], y);
        float zv = __bfloat162float(zp[(size_t)tt*DM]);
        gp[(size_t)tt*DM] = __float2bfloat16_rn(y * zv);
    }
}

// ---------------- launch ----------------
extern "C" void kernel_launch(void* const* d_in, const int* in_sizes, int n_in,
                              void* d_out, int out_size){
    const float* x      = (const float*)d_in[0];
    const float* A_log  = (const float*)d_in[1];
    const float* Bp     = (const float*)d_in[2];
    const float* Cp     = (const float*)d_in[3];
    const float* log_dt = (const float*)d_in[4];
    const float* in_w   = (const float*)d_in[5];
    const float* in_b   = (const float*)d_in[6];
    const float* out_w  = (const float*)d_in[7];
    const float* out_b  = (const float*)d_in[8];
    const float* ln_g   = (const float*)d_in[9];
    const float* ln_b   = (const float*)d_in[10];
    float* outp = (float*)d_out;

    cudaFuncSetAttribute(gemm_hmma<0>, cudaFuncAttributeMaxDynamicSharedMemorySize, GEMM_SMEM);
    cudaFuncSetAttribute(gemm_hmma<1>, cudaFuncAttributeMaxDynamicSharedMemorySize, GEMM_SMEM);

    prep_kernel<<<512, 256>>>(in_w, out_w, A_log, Bp, Cp, log_dt);
    ln_kernel<<<MR, 256>>>(x, ln_g, ln_b);
    gemm_hmma<0><<<dim3(2*DM/256, MR/128), 256, GEMM_SMEM>>>(in_b, nullptr, nullptr);
    ssm_pass1<<<dim3(DM/128, NCH, NB), 128>>>();
    ssm_pass2<<<(NB*DM*DS)/256, 256>>>();
    ssm_pass3<<<dim3(DM/128, NCH, NB), 128>>>();
    gemm_hmma<1><<<dim3(DM/256, MR/128), 256, GEMM_SMEM>>>(out_b, x, outp);
}